// round 2
// baseline (speedup 1.0000x reference)
#include <cuda_runtime.h>
#include <cstdint>
#include <cstddef>

#define NEDGES 500000
#define NNODES 200000

constexpr int TILES = (NEDGES + 127) / 128;   // 3907
constexpr int MROWS = TILES * 128;            // 500096 (padded rows)

// ---------------- device scratch (static globals: allowed) ----------------
__device__ float g_X1[(size_t)MROWS * 512];
__device__ float g_X2[(size_t)MROWS * 512];
__device__ float g_W0r[256 * 512];
__device__ float g_Whr[2 * 512 * 512];
__device__ float g_WHr[512 * 32];   // [pi10 | sigma10 | mu10 | pad2]
__device__ float g_sc[3 * 512];
__device__ float g_sh[3 * 512];
__device__ float g_hb[32];

// ---------------- helpers ----------------
__device__ __forceinline__ float tf32r(float x) {
    unsigned u;
    asm("cvt.rna.tf32.f32 %0, %1;" : "=r"(u) : "f"(x));
    return __uint_as_float(u);
}

__device__ __forceinline__ float actf(float v) {   // ELU then tf32-round
    v = v > 0.f ? v : expm1f(v);
    return tf32r(v);
}

__device__ __forceinline__ void cp16(void* s, const void* g) {
    unsigned ss = (unsigned)__cvta_generic_to_shared(s);
    asm volatile("cp.async.cg.shared.global [%0], [%1], 16;\n" :: "r"(ss), "l"(g));
}
__device__ __forceinline__ void cp_commit() { asm volatile("cp.async.commit_group;\n"); }
template<int N> __device__ __forceinline__ void cp_wait() {
    asm volatile("cp.async.wait_group %0;\n" :: "n"(N) : "memory");
}

__device__ __forceinline__ void mma8(float* c,
                                     unsigned a0, unsigned a1, unsigned a2, unsigned a3,
                                     float fb0, float fb1) {
    unsigned b0 = __float_as_uint(fb0), b1 = __float_as_uint(fb1);
    asm volatile(
        "mma.sync.aligned.m16n8k8.row.col.f32.tf32.tf32.f32 "
        "{%0,%1,%2,%3},{%4,%5,%6,%7},{%8,%9},{%0,%1,%2,%3};"
        : "+f"(c[0]), "+f"(c[1]), "+f"(c[2]), "+f"(c[3])
        : "r"(a0), "r"(a1), "r"(a2), "r"(a3), "r"(b0), "r"(b1));
}

// ---------------- prep: fold BN, round weights to tf32, pack heads ----------------
__global__ void prep_kernel(
    const float* __restrict__ W0,  const float* __restrict__ b0,
    const float* __restrict__ Wh,  const float* __restrict__ bh,
    const float* __restrict__ gm,  const float* __restrict__ bt,
    const float* __restrict__ mn,  const float* __restrict__ vr,
    const float* __restrict__ Wpi, const float* __restrict__ bpi,
    const float* __restrict__ Wsg, const float* __restrict__ bsg,
    const float* __restrict__ Wmu, const float* __restrict__ bmu)
{
    int st = gridDim.x * blockDim.x;
    int t0 = blockIdx.x * blockDim.x + threadIdx.x;
    for (int i = t0; i < 256 * 512; i += st) g_W0r[i] = tf32r(W0[i]);
    for (int i = t0; i < 2 * 512 * 512; i += st) g_Whr[i] = tf32r(Wh[i]);
    for (int i = t0; i < 512 * 32; i += st) {
        int k = i >> 5, n = i & 31;
        float v = (n < 10) ? Wpi[k * 10 + n]
                : (n < 20) ? Wsg[k * 10 + (n - 10)]
                : (n < 30) ? Wmu[k * 10 + (n - 20)] : 0.f;
        g_WHr[i] = tf32r(v);
    }
    for (int i = t0; i < 3 * 512; i += st) {
        int l = i >> 9, c = i & 511;
        float s = gm[i] * rsqrtf(vr[i] + 1e-5f);
        float bb = (l == 0) ? b0[c] : bh[(l - 1) * 512 + c];
        g_sc[i] = s;
        g_sh[i] = (bb - mn[i]) * s + bt[i];
    }
    for (int i = t0; i < 32; i += st)
        g_hb[i] = (i < 10) ? bpi[i] : (i < 20) ? bsg[i - 10] : (i < 30) ? bmu[i - 20] : 0.f;
}

// ---------------- main fused GEMM: out[128xM tile][512] with BN+ELU epilogue ----------------
// grid: (2, TILES); blockIdx.x = N-pass (256 cols), blockIdx.y = row tile. 512 threads.
// Dynamic smem: As[3][128][16] | Bs[3][16][256] | sIdx[256]
template<int KDIM, bool GATHER>
__global__ void __launch_bounds__(512, 1)
gemm_kernel(const float* __restrict__ A,      // GATHER: h [NNODES][128]; else [MROWS][KDIM]
            const int*   __restrict__ edges,  // pl_edge [2][NEDGES] (GATHER only)
            const float* __restrict__ W,      // [KDIM][512] tf32-rounded
            const float* __restrict__ sc,
            const float* __restrict__ sh,
            float* __restrict__ outp)         // [MROWS][512]
{
    extern __shared__ float sm[];
    float* As   = sm;                       // 3 * 2048 floats
    float* Bs   = sm + 3 * 2048;            // 3 * 4096 floats
    int*   sIdx = (int*)(sm + 3 * 2048 + 3 * 4096);

    const int tid  = threadIdx.x;
    const int tile = blockIdx.y;
    const int n0   = blockIdx.x * 256;

    if (GATHER) {
        if (tid < 128) {
            int e = tile * 128 + tid;
            bool v = e < NEDGES;
            sIdx[tid]       = v ? edges[NEDGES + e] : 0;  // cols 0..127  = h[edge[1]]
            sIdx[128 + tid] = v ? edges[e]          : 0;  // cols 128..255 = h[edge[0]]
        }
        __syncthreads();
    }

    constexpr int NC = KDIM / 16;

    auto loadA = [&](int kc, int buf) {
        int r = tid >> 2, seg = tid & 3;      // 512 threads = 128 rows x 4 segs
        float* dst = As + buf * 2048 + r * 16 + seg * 4;
        const float* src;
        if (GATHER) {
            int kk = kc * 16;
            int base = (kk < 128) ? sIdx[r] : sIdx[128 + r];
            src = A + (size_t)base * 128 + (kk & 127) + seg * 4;
        } else {
            src = A + (size_t)(tile * 128 + r) * KDIM + kc * 16 + seg * 4;
        }
        cp16(dst, src);
    };
    auto loadB = [&](int kc, int buf) {
        #pragma unroll
        for (int it = 0; it < 2; it++) {
            int o = tid + it * 512;
            int k = o >> 6, seg = o & 63;
            int col = (seg * 4) ^ (((k >> 2) & 3) << 3);   // xor swizzle
            cp16(Bs + buf * 4096 + k * 256 + col,
                 W + (size_t)(kc * 16 + k) * 512 + n0 + seg * 4);
        }
    };

    const int wid = tid >> 5, lane = tid & 31;
    const int wm = wid >> 3;       // 0..1   (rows wm*64)
    const int wn = wid & 7;        // 0..7   (cols wn*32)
    const int g = lane >> 2, tig = lane & 3;
    const int swz = tig << 3;

    float c[4][4][4];
    #pragma unroll
    for (int i = 0; i < 4; i++)
        #pragma unroll
        for (int j = 0; j < 4; j++)
            #pragma unroll
            for (int q = 0; q < 4; q++) c[i][j][q] = 0.f;

    loadA(0, 0); loadB(0, 0); cp_commit();
    loadA(1, 1); loadB(1, 1); cp_commit();

    #pragma unroll 1
    for (int kc = 0; kc < NC; kc++) {
        int buf = kc % 3;
        __syncthreads();   // protect buffer (kc+2)%3 (computed last iteration)
        if (kc + 2 < NC) {
            loadA(kc + 2, (kc + 2) % 3); loadB(kc + 2, (kc + 2) % 3); cp_commit();
            cp_wait<2>();
        } else if (kc + 1 < NC) {
            cp_wait<1>();
        } else {
            cp_wait<0>();
        }
        __syncthreads();

        const float* Ab = As + buf * 2048;
        const float* Bb = Bs + buf * 4096;

        // hoist B fragments (k permuted: virtual (s,tig,r) <-> actual k = 4*tig+2s+r)
        float b[2][4][2];
        #pragma unroll
        for (int s = 0; s < 2; s++)
            #pragma unroll
            for (int nf = 0; nf < 4; nf++) {
                int n = wn * 32 + nf * 8 + g;
                int col = n ^ swz;
                int k0 = 4 * tig + 2 * s;
                b[s][nf][0] = Bb[k0 * 256 + col];
                b[s][nf][1] = Bb[(k0 + 1) * 256 + col];
            }

        #pragma unroll
        for (int mf = 0; mf < 4; mf++) {
            int r0 = wm * 64 + mf * 16 + g;
            float4 lo = *(const float4*)(Ab + r0 * 16 + 4 * tig);
            float4 hi = *(const float4*)(Ab + (r0 + 8) * 16 + 4 * tig);
            #pragma unroll
            for (int s = 0; s < 2; s++) {
                unsigned a0 = __float_as_uint(s ? lo.z : lo.x);
                unsigned a2 = __float_as_uint(s ? lo.w : lo.y);
                unsigned a1 = __float_as_uint(s ? hi.z : hi.x);
                unsigned a3 = __float_as_uint(s ? hi.w : hi.y);
                #pragma unroll
                for (int nf = 0; nf < 4; nf++)
                    mma8(c[mf][nf], a0, a1, a2, a3, b[s][nf][0], b[s][nf][1]);
            }
        }
    }

    // epilogue: y = s*acc + t, ELU, tf32-round, store
    size_t rowbase = (size_t)tile * 128;
    #pragma unroll
    for (int mf = 0; mf < 4; mf++) {
        int r0 = wm * 64 + mf * 16 + g;
        #pragma unroll
        for (int nf = 0; nf < 4; nf++) {
            int col = n0 + wn * 32 + nf * 8 + 2 * tig;
            float s0 = __ldg(sc + col), s1 = __ldg(sc + col + 1);
            float t0 = __ldg(sh + col), t1 = __ldg(sh + col + 1);
            float2 v01, v23;
            v01.x = actf(s0 * c[mf][nf][0] + t0);
            v01.y = actf(s1 * c[mf][nf][1] + t1);
            v23.x = actf(s0 * c[mf][nf][2] + t0);
            v23.y = actf(s1 * c[mf][nf][3] + t1);
            *(float2*)(outp + (rowbase + r0) * 512 + col)     = v01;
            *(float2*)(outp + (rowbase + r0 + 8) * 512 + col) = v23;
        }
    }
}

// ---------------- head kernel: [128][512] @ [512][32] + softmax/ELU + dist ----------------
__global__ void __launch_bounds__(256, 1)
head_kernel(const float* __restrict__ A,     // [MROWS][512]
            const float* __restrict__ W,     // [512][32]
            const float* __restrict__ dist,
            float* __restrict__ out)
{
    __shared__ __align__(16) float As[2][128][16];
    __shared__ __align__(16) float Bs[2][16][32];
    __shared__ float sZ[128][33];

    const int tid = threadIdx.x;
    const int tile = blockIdx.x;

    auto loadA = [&](int kc, int buf) {
        #pragma unroll
        for (int it = 0; it < 2; it++) {
            int o = tid + it * 256;
            int r = o >> 2, seg = o & 3;
            cp16(&As[buf][r][seg * 4],
                 A + (size_t)(tile * 128 + r) * 512 + kc * 16 + seg * 4);
        }
    };
    auto loadB = [&](int kc, int buf) {
        if (tid < 128) {
            int k = tid >> 3, seg = tid & 7;
            int col = (seg * 4) ^ (((k >> 2) & 3) << 3);
            cp16(&Bs[buf][k][col], W + (size_t)(kc * 16 + k) * 32 + seg * 4);
        }
    };

    const int wid = tid >> 5, lane = tid & 31;
    const int wm = wid;                 // 0..7 -> rows wm*16
    const int g = lane >> 2, tig = lane & 3;
    const int swz = tig << 3;

    float c[4][4];
    #pragma unroll
    for (int i = 0; i < 4; i++)
        #pragma unroll
        for (int q = 0; q < 4; q++) c[i][q] = 0.f;

    loadA(0, 0); loadB(0, 0); cp_commit();

    #pragma unroll 1
    for (int kc = 0; kc < 32; kc++) {
        int buf = kc & 1;
        __syncthreads();
        if (kc + 1 < 32) { loadA(kc + 1, buf ^ 1); loadB(kc + 1, buf ^ 1); cp_commit(); cp_wait<1>(); }
        else             { cp_wait<0>(); }
        __syncthreads();

        float b[2][4][2];
        #pragma unroll
        for (int s = 0; s < 2; s++)
            #pragma unroll
            for (int nf = 0; nf < 4; nf++) {
                int col = (nf * 8 + g) ^ swz;
                int k0 = 4 * tig + 2 * s;
                b[s][nf][0] = Bs[buf][k0][col];
                b[s][nf][1] = Bs[buf][k0 + 1][col];
            }
        int r0 = wm * 16 + g;
        float4 lo = *(const float4*)(&As[buf][r0][4 * tig]);
        float4 hi = *(const float4*)(&As[buf][r0 + 8][4 * tig]);
        #pragma unroll
        for (int s = 0; s < 2; s++) {
            unsigned a0 = __float_as_uint(s ? lo.z : lo.x);
            unsigned a2 = __float_as_uint(s ? lo.w : lo.y);
            unsigned a1 = __float_as_uint(s ? hi.z : hi.x);
            unsigned a3 = __float_as_uint(s ? hi.w : hi.y);
            #pragma unroll
            for (int nf = 0; nf < 4; nf++)
                mma8(c[nf], a0, a1, a2, a3, b[s][nf][0], b[s][nf][1]);
        }
    }

    // dump accumulators to smem
    {
        int r0 = wm * 16 + g;
        #pragma unroll
        for (int nf = 0; nf < 4; nf++) {
            int co = nf * 8 + 2 * tig;
            sZ[r0][co]     = c[nf][0];
            sZ[r0][co + 1] = c[nf][1];
            sZ[r0 + 8][co]     = c[nf][2];
            sZ[r0 + 8][co + 1] = c[nf][3];
        }
    }
    __syncthreads();

    if (tid < 128) {
        int e = tile * 128 + tid;
        if (e < NEDGES) {
            float z[30];
            #pragma unroll
            for (int k = 0; k < 30; k++) z[k] = sZ[tid][k] + g_hb[k];
            // softmax over z[0..9]
            float m = z[0];
            #pragma unroll
            for (int k = 1; k < 10; k++) m = fmaxf(m, z[k]);
            float ez[10], sum = 0.f;
            #pragma unroll
            for (int k = 0; k < 10; k++) { ez[k] = expf(z[k] - m); sum += ez[k]; }
            float inv = 1.f / sum;
            #pragma unroll
            for (int k = 0; k < 10; k++) out[(size_t)e * 10 + k] = ez[k] * inv;
            #pragma unroll
            for (int k = 0; k < 10; k++) {
                float v = z[10 + k];
                v = v > 0.f ? v : expm1f(v);
                out[5000000u + (size_t)e * 10 + k] = v + 1.1f;
            }
            #pragma unroll
            for (int k = 0; k < 10; k++) {
                float v = z[20 + k];
                v = v > 0.f ? v : expm1f(v);
                out[10000000u + (size_t)e * 10 + k] = v + 1.0f;
            }
            out[15000000u + e] = __ldg(dist + e);
        }
    }
}

// ---------------- launch ----------------
extern "C" void kernel_launch(void* const* d_in, const int* in_sizes, int n_in,
                              void* d_out, int out_size) {
    (void)in_sizes; (void)n_in; (void)out_size;
    const float* h    = (const float*)d_in[0];
    const int*   edges= (const int*)  d_in[1];
    const float* dist = (const float*)d_in[2];
    const float* W0   = (const float*)d_in[3];
    const float* b0   = (const float*)d_in[4];
    const float* Wh   = (const float*)d_in[5];
    const float* bh   = (const float*)d_in[6];
    const float* gm   = (const float*)d_in[7];
    const float* bt   = (const float*)d_in[8];
    const float* mn   = (const float*)d_in[9];
    const float* vr   = (const float*)d_in[10];
    const float* Wpi  = (const float*)d_in[11];
    const float* bpi  = (const float*)d_in[12];
    const float* Wsg  = (const float*)d_in[13];
    const float* bsg  = (const float*)d_in[14];
    const float* Wmu  = (const float*)d_in[15];
    const float* bmu  = (const float*)d_in[16];
    float* out = (float*)d_out;

    const int SMEM = (3 * 2048 + 3 * 4096) * 4 + 256 * 4;   // 74752 B
    cudaFuncSetAttribute(gemm_kernel<256, true>,  cudaFuncAttributeMaxDynamicSharedMemorySize, SMEM);
    cudaFuncSetAttribute(gemm_kernel<512, false>, cudaFuncAttributeMaxDynamicSharedMemorySize, SMEM);

    float *X1, *X2, *W0r, *Whr, *WHr, *sc, *sh;
    cudaGetSymbolAddress((void**)&X1,  g_X1);
    cudaGetSymbolAddress((void**)&X2,  g_X2);
    cudaGetSymbolAddress((void**)&W0r, g_W0r);
    cudaGetSymbolAddress((void**)&Whr, g_Whr);
    cudaGetSymbolAddress((void**)&WHr, g_WHr);
    cudaGetSymbolAddress((void**)&sc,  g_sc);
    cudaGetSymbolAddress((void**)&sh,  g_sh);

    prep_kernel<<<256, 256>>>(W0, b0, Wh, bh, gm, bt, mn, vr,
                              Wpi, bpi, Wsg, bsg, Wmu, bmu);

    dim3 grid(2, TILES);
    gemm_kernel<256, true ><<<grid, 512, SMEM>>>(h,  edges,   W0r,           sc,        sh,        X1);
    gemm_kernel<512, false><<<grid, 512, SMEM>>>(X1, nullptr, Whr,           sc + 512,  sh + 512,  X2);
    gemm_kernel<512, false><<<grid, 512, SMEM>>>(X2, nullptr, Whr + 262144,  sc + 1024, sh + 1024, X1);
    head_kernel<<<TILES, 256>>>(X1, WHr, dist, out);
}

// round 3
// speedup vs baseline: 1.0979x; 1.0979x over previous
#include <cuda_runtime.h>
#include <cstdint>
#include <cstddef>

#define NEDGES 500000
#define NNODES 200000

constexpr int TILES = (NEDGES + 127) / 128;   // 3907
constexpr int MROWS = TILES * 128;            // 500096

// ---------------- device scratch (static globals: allowed) ----------------
__device__ float g_X1[(size_t)MROWS * 512];
__device__ float g_X2[(size_t)MROWS * 512];
__device__ float g_W0t[8 * 512 * 32];         // layer1 W, chunk-major [kc][n][k]
__device__ float g_Wht[2 * 16 * 512 * 32];    // hidden Ws, chunk-major
__device__ float g_WHt[32 * 512];             // head W, n-major [n][k]
__device__ float g_sc[3 * 512];
__device__ float g_sh[3 * 512];
__device__ float g_hb[32];

// ---------------- helpers ----------------
__device__ __forceinline__ float tf32r(float x) {
    unsigned u;
    asm("cvt.rna.tf32.f32 %0, %1;" : "=r"(u) : "f"(x));
    return __uint_as_float(u);
}
__device__ __forceinline__ float actf(float v) {   // ELU then tf32-round
    v = v > 0.f ? v : expm1f(v);
    return tf32r(v);
}
__device__ __forceinline__ void cp16(void* s, const void* g) {
    unsigned ss = (unsigned)__cvta_generic_to_shared(s);
    asm volatile("cp.async.cg.shared.global [%0], [%1], 16;\n" :: "r"(ss), "l"(g));
}
__device__ __forceinline__ void cp_commit() { asm volatile("cp.async.commit_group;\n"); }
template<int N> __device__ __forceinline__ void cp_wait() {
    asm volatile("cp.async.wait_group %0;\n" :: "n"(N) : "memory");
}
__device__ __forceinline__ void mma8(float* c,
                                     unsigned a0, unsigned a1, unsigned a2, unsigned a3,
                                     float fb0, float fb1) {
    unsigned b0 = __float_as_uint(fb0), b1 = __float_as_uint(fb1);
    asm volatile(
        "mma.sync.aligned.m16n8k8.row.col.f32.tf32.tf32.f32 "
        "{%0,%1,%2,%3},{%4,%5,%6,%7},{%8,%9},{%0,%1,%2,%3};"
        : "+f"(c[0]), "+f"(c[1]), "+f"(c[2]), "+f"(c[3])
        : "r"(a0), "r"(a1), "r"(a2), "r"(a3), "r"(b0), "r"(b1));
}

// smem xor swizzles (flip bits 4 and 2 of the k-position based on low n / r bits)
__device__ __forceinline__ int bswz_of(int n) { return ((n & 1) << 4) | ((n & 2) << 1); }

// ---------------- prep: fold BN, transpose+round weights, pack heads ----------------
__global__ void prep_kernel(
    const float* __restrict__ W0,  const float* __restrict__ b0,
    const float* __restrict__ Wh,  const float* __restrict__ bh,
    const float* __restrict__ gm,  const float* __restrict__ bt,
    const float* __restrict__ mn,  const float* __restrict__ vr,
    const float* __restrict__ Wpi, const float* __restrict__ bpi,
    const float* __restrict__ Wsg, const float* __restrict__ bsg,
    const float* __restrict__ Wmu, const float* __restrict__ bmu)
{
    int st = gridDim.x * blockDim.x;
    int t0 = blockIdx.x * blockDim.x + threadIdx.x;
    // layer-1 weights: g_W0t[kc][n][kk] = tf32(W0[kc*32+kk][n])
    for (int o = t0; o < 8 * 512 * 32; o += st) {
        int kc = o >> 14, n = (o >> 5) & 511, kk = o & 31;
        g_W0t[o] = tf32r(W0[(size_t)(kc * 32 + kk) * 512 + n]);
    }
    // hidden weights
    for (int o = t0; o < 2 * 16 * 512 * 32; o += st) {
        int l = o >> 18;
        int kc = (o >> 14) & 15, n = (o >> 5) & 511, kk = o & 31;
        g_Wht[o] = tf32r(Wh[(size_t)l * 262144 + (size_t)(kc * 32 + kk) * 512 + n]);
    }
    // head weights n-major
    for (int o = t0; o < 32 * 512; o += st) {
        int n = o >> 9, k = o & 511;
        float v = (n < 10) ? Wpi[k * 10 + n]
                : (n < 20) ? Wsg[k * 10 + (n - 10)]
                : (n < 30) ? Wmu[k * 10 + (n - 20)] : 0.f;
        g_WHt[o] = tf32r(v);
    }
    for (int i = t0; i < 3 * 512; i += st) {
        int l = i >> 9, c = i & 511;
        float s = gm[i] * rsqrtf(vr[i] + 1e-5f);
        float bb = (l == 0) ? b0[c] : bh[(l - 1) * 512 + c];
        g_sc[i] = s;
        g_sh[i] = (bb - mn[i]) * s + bt[i];
    }
    for (int i = t0; i < 32; i += st)
        g_hb[i] = (i < 10) ? bpi[i] : (i < 20) ? bsg[i - 10] : (i < 30) ? bmu[i - 20] : 0.f;
}

// ---------------- main fused GEMM ----------------
// grid (2, TILES), 512 threads. CTA tile: M=128 x N=256. K chunk = 32, 4-stage pipeline.
// smem: As[4][128][32] (r-parity swizzled) | Bs[4][256][32] (n-low-bit swizzled) | sIdx[256]
template<int KDIM, bool GATHER>
__global__ void __launch_bounds__(512, 1)
gemm_kernel(const float* __restrict__ A,      // GATHER: h [NNODES][128]; else [MROWS][KDIM]
            const int*   __restrict__ edges,
            const float* __restrict__ W,      // chunk-major [KDIM/32][512][32], tf32
            const float* __restrict__ sc,
            const float* __restrict__ sh,
            float* __restrict__ outp)
{
    extern __shared__ float sm[];
    float* As   = sm;                    // 4 * 4096
    float* Bs   = sm + 16384;            // 4 * 8192
    int*   sIdx = (int*)(sm + 16384 + 32768);

    const int tid  = threadIdx.x;
    const int tile = blockIdx.y;
    const int n0   = blockIdx.x * 256;

    if (GATHER) {
        if (tid < 128) {
            int e = tile * 128 + tid;
            bool v = e < NEDGES;
            sIdx[tid]       = v ? edges[NEDGES + e] : 0;   // cols 0..127  = h[edge[1]]
            sIdx[128 + tid] = v ? edges[e]          : 0;   // cols 128..255 = h[edge[0]]
        }
        __syncthreads();
    }

    constexpr int NC = KDIM / 32;

    auto loadA = [&](int kc, int buf) {
        #pragma unroll
        for (int it = 0; it < 2; it++) {
            int o = tid + it * 512;
            int r = o >> 3, seg = o & 7;
            float* dst = As + buf * 4096 + r * 32 + ((seg * 4) ^ ((r & 1) << 4));
            const float* src;
            if (GATHER) {
                int base = (kc < 4) ? sIdx[r] : sIdx[128 + r];
                src = A + (size_t)base * 128 + (kc & 3) * 32 + seg * 4;
            } else {
                src = A + (size_t)(tile * 128 + r) * KDIM + kc * 32 + seg * 4;
            }
            cp16(dst, src);
        }
    };
    auto loadB = [&](int kc, int buf) {
        const float* src = W + (size_t)kc * 16384 + (size_t)n0 * 32;
        #pragma unroll
        for (int it = 0; it < 4; it++) {
            int o = tid + it * 512;
            int n = o >> 3, seg = o & 7;
            float* dst = Bs + buf * 8192 + n * 32 + ((seg * 4) ^ bswz_of(n));
            cp16(dst, src + o * 4);
        }
    };

    const int wid = tid >> 5, lane = tid & 31;
    const int wm = wid >> 3;       // rows wm*64
    const int wn = wid & 7;        // cols wn*32
    const int g = lane >> 2, tig = lane & 3;
    const int aswz = (g & 1) << 4;
    const int bswz = bswz_of(g);   // n low bits == g low bits
    int koffA[2], koffB[2];
    koffA[0] = (4 * tig) ^ aswz;  koffA[1] = (16 + 4 * tig) ^ aswz;
    koffB[0] = (4 * tig) ^ bswz;  koffB[1] = (16 + 4 * tig) ^ bswz;
    const float* pA = As + (wm * 64 + g) * 32;
    const float* pB = Bs + (wn * 32 + g) * 32;

    float c[4][4][4];
    #pragma unroll
    for (int i = 0; i < 4; i++)
        #pragma unroll
        for (int j = 0; j < 4; j++)
            #pragma unroll
            for (int q = 0; q < 4; q++) c[i][j][q] = 0.f;

    loadA(0, 0); loadB(0, 0); cp_commit();
    loadA(1, 1); loadB(1, 1); cp_commit();

    #pragma unroll 1
    for (int kc = 0; kc < NC; kc++) {
        if (kc + 2 < NC) { loadA(kc + 2, (kc + 2) & 3); loadB(kc + 2, (kc + 2) & 3); cp_commit(); cp_wait<2>(); }
        else if (kc + 1 < NC) cp_wait<1>();
        else cp_wait<0>();
        __syncthreads();   // single barrier: reload target buffer is 2 barriers old

        const float* Ab = pA + (kc & 3) * 4096;
        const float* Bb = pB + (kc & 3) * 8192;

        #pragma unroll
        for (int h = 0; h < 2; h++) {
            float4 bb[4];
            #pragma unroll
            for (int nf = 0; nf < 4; nf++)
                bb[nf] = *(const float4*)(Bb + nf * 256 + koffB[h]);
            #pragma unroll
            for (int mf = 0; mf < 4; mf++) {
                float4 lo = *(const float4*)(Ab + mf * 512 + koffA[h]);
                float4 hi = *(const float4*)(Ab + mf * 512 + 256 + koffA[h]);
                #pragma unroll
                for (int s = 0; s < 2; s++) {
                    unsigned a0 = __float_as_uint(s ? lo.z : lo.x);
                    unsigned a2 = __float_as_uint(s ? lo.w : lo.y);
                    unsigned a1 = __float_as_uint(s ? hi.z : hi.x);
                    unsigned a3 = __float_as_uint(s ? hi.w : hi.y);
                    #pragma unroll
                    for (int nf = 0; nf < 4; nf++)
                        mma8(c[mf][nf], a0, a1, a2, a3,
                             s ? bb[nf].z : bb[nf].x, s ? bb[nf].w : bb[nf].y);
                }
            }
        }
    }

    // epilogue: y = s*acc + t, ELU, tf32-round
    size_t rowbase = (size_t)tile * 128;
    #pragma unroll
    for (int nf = 0; nf < 4; nf++) {
        int col = n0 + wn * 32 + nf * 8 + 2 * tig;
        float s0 = __ldg(sc + col), s1 = __ldg(sc + col + 1);
        float t0 = __ldg(sh + col), t1 = __ldg(sh + col + 1);
        #pragma unroll
        for (int mf = 0; mf < 4; mf++) {
            int r0 = wm * 64 + mf * 16 + g;
            float2 v01, v23;
            v01.x = actf(s0 * c[mf][nf][0] + t0);
            v01.y = actf(s1 * c[mf][nf][1] + t1);
            v23.x = actf(s0 * c[mf][nf][2] + t0);
            v23.y = actf(s1 * c[mf][nf][3] + t1);
            *(float2*)(outp + (rowbase + r0) * 512 + col)     = v01;
            *(float2*)(outp + (rowbase + r0 + 8) * 512 + col) = v23;
        }
    }
}

// ---------------- head kernel: [128][512] @ [512][32] + softmax/ELU + dist ----------------
// B (64KB) resident in smem; A double-buffered K32 chunks.
// smem: Bp[32][512] swizzled | As[2][128][32] | sZ[128][33]
__global__ void __launch_bounds__(256, 1)
head_kernel(const float* __restrict__ A,
            const float* __restrict__ Wt,    // [32 n][512 k] tf32
            const float* __restrict__ dist,
            float* __restrict__ out)
{
    extern __shared__ float hsm[];
    float* Bp = hsm;                 // 16384
    float* As = hsm + 16384;         // 8192
    float* sZ = hsm + 16384 + 8192;  // 128*33

    const int tid  = threadIdx.x;
    const int tile = blockIdx.x;

    // load full head-weight tile once (group 0 also carries A chunk 0)
    #pragma unroll
    for (int it = 0; it < 16; it++) {
        int o = tid + it * 256;
        int n = o >> 7, ks = o & 127;
        cp16(Bp + n * 512 + ((ks * 4) ^ bswz_of(n)), Wt + (size_t)n * 512 + ks * 4);
    }

    auto loadA = [&](int kc, int buf) {
        #pragma unroll
        for (int it = 0; it < 4; it++) {
            int o = tid + it * 256;
            int r = o >> 3, seg = o & 7;
            cp16(As + buf * 4096 + r * 32 + ((seg * 4) ^ ((r & 1) << 4)),
                 A + (size_t)(tile * 128 + r) * 512 + kc * 32 + seg * 4);
        }
    };

    const int wid = tid >> 5, lane = tid & 31;   // wid 0..7 -> rows wid*16
    const int g = lane >> 2, tig = lane & 3;
    const int aswz = (g & 1) << 4;
    const int bswz = bswz_of(g);
    int koffA[2], koffB[2];
    koffA[0] = (4 * tig) ^ aswz;  koffA[1] = (16 + 4 * tig) ^ aswz;
    koffB[0] = (4 * tig) ^ bswz;  koffB[1] = (16 + 4 * tig) ^ bswz;
    const float* pA = As + (wid * 16 + g) * 32;
    const float* pB = Bp + g * 512;

    float c[4][4];
    #pragma unroll
    for (int i = 0; i < 4; i++)
        #pragma unroll
        for (int q = 0; q < 4; q++) c[i][q] = 0.f;

    loadA(0, 0); cp_commit();

    #pragma unroll 1
    for (int kc = 0; kc < 16; kc++) {
        int buf = kc & 1;
        __syncthreads();
        if (kc + 1 < 16) { loadA(kc + 1, buf ^ 1); cp_commit(); cp_wait<1>(); }
        else             { cp_wait<0>(); }
        __syncthreads();

        const float* Ab = pA + buf * 4096;
        const float* Bb = pB + kc * 32;
        #pragma unroll
        for (int h = 0; h < 2; h++) {
            float4 bb[4];
            #pragma unroll
            for (int nf = 0; nf < 4; nf++)
                bb[nf] = *(const float4*)(Bb + nf * 4096 + koffB[h]);
            float4 lo = *(const float4*)(Ab + koffA[h]);
            float4 hi = *(const float4*)(Ab + 256 + koffA[h]);
            #pragma unroll
            for (int s = 0; s < 2; s++) {
                unsigned a0 = __float_as_uint(s ? lo.z : lo.x);
                unsigned a2 = __float_as_uint(s ? lo.w : lo.y);
                unsigned a1 = __float_as_uint(s ? hi.z : hi.x);
                unsigned a3 = __float_as_uint(s ? hi.w : hi.y);
                #pragma unroll
                for (int nf = 0; nf < 4; nf++)
                    mma8(c[nf], a0, a1, a2, a3,
                         s ? bb[nf].z : bb[nf].x, s ? bb[nf].w : bb[nf].y);
            }
        }
    }

    // dump accumulators to smem
    {
        int r0 = wid * 16 + g;
        #pragma unroll
        for (int nf = 0; nf < 4; nf++) {
            int co = nf * 8 + 2 * tig;
            sZ[r0 * 33 + co]           = c[nf][0];
            sZ[r0 * 33 + co + 1]       = c[nf][1];
            sZ[(r0 + 8) * 33 + co]     = c[nf][2];
            sZ[(r0 + 8) * 33 + co + 1] = c[nf][3];
        }
    }
    __syncthreads();

    if (tid < 128) {
        int e = tile * 128 + tid;
        if (e < NEDGES) {
            float z[30];
            #pragma unroll
            for (int k = 0; k < 30; k++) z[k] = sZ[tid * 33 + k] + g_hb[k];
            float m = z[0];
            #pragma unroll
            for (int k = 1; k < 10; k++) m = fmaxf(m, z[k]);
            float ez[10], sum = 0.f;
            #pragma unroll
            for (int k = 0; k < 10; k++) { ez[k] = expf(z[k] - m); sum += ez[k]; }
            float inv = 1.f / sum;
            #pragma unroll
            for (int k = 0; k < 10; k++) out[(size_t)e * 10 + k] = ez[k] * inv;
            #pragma unroll
            for (int k = 0; k < 10; k++) {
                float v = z[10 + k];
                v = v > 0.f ? v : expm1f(v);
                out[5000000u + (size_t)e * 10 + k] = v + 1.1f;
            }
            #pragma unroll
            for (int k = 0; k < 10; k++) {
                float v = z[20 + k];
                v = v > 0.f ? v : expm1f(v);
                out[10000000u + (size_t)e * 10 + k] = v + 1.0f;
            }
            out[15000000u + e] = __ldg(dist + e);
        }
    }
}

// ---------------- launch ----------------
extern "C" void kernel_launch(void* const* d_in, const int* in_sizes, int n_in,
                              void* d_out, int out_size) {
    (void)in_sizes; (void)n_in; (void)out_size;
    const float* h    = (const float*)d_in[0];
    const int*   edges= (const int*)  d_in[1];
    const float* dist = (const float*)d_in[2];
    const float* W0   = (const float*)d_in[3];
    const float* b0   = (const float*)d_in[4];
    const float* Wh   = (const float*)d_in[5];
    const float* bh   = (const float*)d_in[6];
    const float* gm   = (const float*)d_in[7];
    const float* bt   = (const float*)d_in[8];
    const float* mn   = (const float*)d_in[9];
    const float* vr   = (const float*)d_in[10];
    const float* Wpi  = (const float*)d_in[11];
    const float* bpi  = (const float*)d_in[12];
    const float* Wsg  = (const float*)d_in[13];
    const float* bsg  = (const float*)d_in[14];
    const float* Wmu  = (const float*)d_in[15];
    const float* bmu  = (const float*)d_in[16];
    float* out = (float*)d_out;

    const int SMEM_MAIN = (16384 + 32768 + 256) * 4;                 // 197,632 B
    const int SMEM_HEAD = (16384 + 8192 + 128 * 33) * 4;             // 115,200 B
    cudaFuncSetAttribute(gemm_kernel<256, true>,  cudaFuncAttributeMaxDynamicSharedMemorySize, SMEM_MAIN);
    cudaFuncSetAttribute(gemm_kernel<512, false>, cudaFuncAttributeMaxDynamicSharedMemorySize, SMEM_MAIN);
    cudaFuncSetAttribute(head_kernel,             cudaFuncAttributeMaxDynamicSharedMemorySize, SMEM_HEAD);

    float *X1, *X2, *W0t, *Wht, *WHt, *sc, *sh;
    cudaGetSymbolAddress((void**)&X1,  g_X1);
    cudaGetSymbolAddress((void**)&X2,  g_X2);
    cudaGetSymbolAddress((void**)&W0t, g_W0t);
    cudaGetSymbolAddress((void**)&Wht, g_Wht);
    cudaGetSymbolAddress((void**)&WHt, g_WHt);
    cudaGetSymbolAddress((void**)&sc,  g_sc);
    cudaGetSymbolAddress((void**)&sh,  g_sh);

    prep_kernel<<<256, 256>>>(W0, b0, Wh, bh, gm, bt, mn, vr,
                              Wpi, bpi, Wsg, bsg, Wmu, bmu);

    dim3 grid(2, TILES);
    gemm_kernel<256, true ><<<grid, 512, SMEM_MAIN>>>(h,  edges,   W0t,                 sc,         sh,         X1);
    gemm_kernel<512, false><<<grid, 512, SMEM_MAIN>>>(X1, nullptr, Wht,                 sc + 512,   sh + 512,   X2);
    gemm_kernel<512, false><<<grid, 512, SMEM_MAIN>>>(X2, nullptr, Wht + 16 * 512 * 32, sc + 1024,  sh + 1024,  X1);
    head_kernel<<<TILES, 256, SMEM_HEAD>>>(X1, WHt, dist, out);
}

// round 5
// speedup vs baseline: 1.2342x; 1.1242x over previous
#include <cuda_runtime.h>
#include <cstdint>
#include <cstddef>

#define NEDGES 500000
#define NNODES 200000

constexpr int TILES = (NEDGES + 127) / 128;   // 3907
constexpr int MROWS = TILES * 128;            // 500096

// ---------------- device scratch (static globals: allowed) ----------------
__device__ float g_X1[(size_t)MROWS * 512];
__device__ float g_X2[(size_t)MROWS * 512];
__device__ float g_W0t[8 * 512 * 32];         // layer1 W, chunk-major [kc][n][k] tf32
__device__ float g_Wht[2 * 16 * 512 * 32];    // hidden Ws, chunk-major tf32
__device__ float g_WHt[32 * 512];             // head W, n-major [n][k] tf32
__device__ float g_sc[3 * 512];
__device__ float g_sh[3 * 512];
__device__ float g_hb[32];

// ---------------- helpers ----------------
__device__ __forceinline__ float tf32r(float x) {
    unsigned u;
    asm("cvt.rna.tf32.f32 %0, %1;" : "=r"(u) : "f"(x));
    return __uint_as_float(u);
}
__device__ __forceinline__ float actf(float v) {   // ELU then tf32-round
    v = v > 0.f ? v : expm1f(v);
    return tf32r(v);
}
__device__ __forceinline__ void cp16(void* s, const void* g) {
    unsigned ss = (unsigned)__cvta_generic_to_shared(s);
    asm volatile("cp.async.cg.shared.global [%0], [%1], 16;\n" :: "r"(ss), "l"(g));
}
__device__ __forceinline__ void cp16s(uint32_t s, const void* g) {
    asm volatile("cp.async.cg.shared.global [%0], [%1], 16;\n" :: "r"(s), "l"(g));
}
__device__ __forceinline__ void cp_commit() { asm volatile("cp.async.commit_group;\n"); }
template<int N> __device__ __forceinline__ void cp_wait() {
    asm volatile("cp.async.wait_group %0;\n" :: "n"(N) : "memory");
}
__device__ __forceinline__ void mma8(float* c,
                                     unsigned a0, unsigned a1, unsigned a2, unsigned a3,
                                     float fb0, float fb1) {
    unsigned b0 = __float_as_uint(fb0), b1 = __float_as_uint(fb1);
    asm volatile(
        "mma.sync.aligned.m16n8k8.row.col.f32.tf32.tf32.f32 "
        "{%0,%1,%2,%3},{%4,%5,%6,%7},{%8,%9},{%0,%1,%2,%3};"
        : "+f"(c[0]), "+f"(c[1]), "+f"(c[2]), "+f"(c[3])
        : "r"(a0), "r"(a1), "r"(a2), "r"(a3), "r"(b0), "r"(b1));
}
__device__ __forceinline__ int bswz_of(int n) { return ((n & 1) << 4) | ((n & 2) << 1); }

// ---------------- prep: fold BN, transpose+round weights, pack heads ----------------
__global__ void prep_kernel(
    const float* __restrict__ W0,  const float* __restrict__ b0,
    const float* __restrict__ Wh,  const float* __restrict__ bh,
    const float* __restrict__ gm,  const float* __restrict__ bt,
    const float* __restrict__ mn,  const float* __restrict__ vr,
    const float* __restrict__ Wpi, const float* __restrict__ bpi,
    const float* __restrict__ Wsg, const float* __restrict__ bsg,
    const float* __restrict__ Wmu, const float* __restrict__ bmu)
{
    int st = gridDim.x * blockDim.x;
    int t0 = blockIdx.x * blockDim.x + threadIdx.x;
    for (int o = t0; o < 8 * 512 * 32; o += st) {
        int kc = o >> 14, n = (o >> 5) & 511, kk = o & 31;
        g_W0t[o] = tf32r(W0[(size_t)(kc * 32 + kk) * 512 + n]);
    }
    for (int o = t0; o < 2 * 16 * 512 * 32; o += st) {
        int l = o >> 18;
        int kc = (o >> 14) & 15, n = (o >> 5) & 511, kk = o & 31;
        g_Wht[o] = tf32r(Wh[(size_t)l * 262144 + (size_t)(kc * 32 + kk) * 512 + n]);
    }
    for (int o = t0; o < 32 * 512; o += st) {
        int n = o >> 9, k = o & 511;
        float v = (n < 10) ? Wpi[k * 10 + n]
                : (n < 20) ? Wsg[k * 10 + (n - 10)]
                : (n < 30) ? Wmu[k * 10 + (n - 20)] : 0.f;
        g_WHt[o] = tf32r(v);
    }
    for (int i = t0; i < 3 * 512; i += st) {
        int l = i >> 9, c = i & 511;
        float s = gm[i] * rsqrtf(vr[i] + 1e-5f);
        float bb = (l == 0) ? b0[c] : bh[(l - 1) * 512 + c];
        g_sc[i] = s;
        g_sh[i] = (bb - mn[i]) * s + bt[i];
    }
    for (int i = t0; i < 32; i += st)
        g_hb[i] = (i < 10) ? bpi[i] : (i < 20) ? bsg[i - 10] : (i < 30) ? bmu[i - 20] : 0.f;
}

// ---------------- main fused GEMM ----------------
// CTA tile M=128 x N=128, 256 threads, 2 CTAs/SM. K chunk 32, 3-stage cp.async ring.
// grid (4 n-passes, TILES).
// smem floats: As[3][128][32] | Bs[3][128][32] @12288 | sIdx[256] @24576
constexpr int SMEM_MAIN_F = 24576 + 256;
constexpr int SMEM_MAIN_B = SMEM_MAIN_F * 4;   // 99,328 B  (2 CTAs: 198,656 <= 228KB)

template<int KDIM, bool GATHER>
__global__ void __launch_bounds__(256, 2)
gemm_kernel(const float* __restrict__ Ag,     // GATHER: h [NNODES][128]; else [MROWS][KDIM]
            const int*   __restrict__ edges,
            const float* __restrict__ W,      // chunk-major [KDIM/32][512][32] tf32
            const float* __restrict__ sc,
            const float* __restrict__ sh,
            float* __restrict__ outp)
{
    extern __shared__ float sm[];
    float* As   = sm;                 // 3 * 4096
    float* Bs   = sm + 12288;         // 3 * 4096
    int*   sIdx = (int*)(sm + 24576);

    const int tid  = threadIdx.x;
    const int tile = blockIdx.y;
    const int n0   = blockIdx.x * 128;
    constexpr int NC = KDIM / 32;

    if (GATHER) {
        if (tid < 128) {
            int e = tile * 128 + tid;
            bool v = e < NEDGES;
            sIdx[tid]       = v ? edges[NEDGES + e] : 0;   // k 0..127   = h[edge[1]]
            sIdx[128 + tid] = v ? edges[e]          : 0;   // k 128..255 = h[edge[0]]
        }
        __syncthreads();
    }

    // ---- hoisted cp.async descriptors ----
    // o = tid + it*256  ->  seg = tid&7 (it-invariant), r = (tid>>3) + it*32.
    const int seg = tid & 7;
    const int r0  = tid >> 3;
    const uint32_t sAb = (uint32_t)__cvta_generic_to_shared(As);
    const uint32_t sBb = (uint32_t)__cvta_generic_to_shared(Bs);
    const uint32_t dA0 = sAb + (uint32_t)(r0 * 32 + ((seg * 4) ^ ((r0 & 1) << 4))) * 4;
    const uint32_t dB0 = sBb + (uint32_t)(r0 * 32 + ((seg * 4) ^ bswz_of(r0))) * 4;
    const float* srcA0 = GATHER ? Ag : (Ag + (size_t)(tile * 128 + r0) * KDIM + seg * 4);
    const float* srcB0 = W + (size_t)(n0 + r0) * 32 + seg * 4;

    auto prefetch = [&](int kc) {
        uint32_t so = (uint32_t)(kc % 3) * 16384;   // stage byte offset
        if (GATHER) {
            const int half = (kc < 4) ? 0 : 128;
            const int kof  = (kc & 3) * 32 + seg * 4;
            #pragma unroll
            for (int it = 0; it < 4; it++) {
                int node = sIdx[half + r0 + it * 32];
                cp16s(dA0 + so + it * 4096, Ag + (size_t)node * 128 + kof);
            }
        } else {
            const float* s = srcA0 + kc * 32;
            #pragma unroll
            for (int it = 0; it < 4; it++)
                cp16s(dA0 + so + it * 4096, s + (size_t)it * 32 * KDIM);
        }
        const float* sb = srcB0 + (size_t)kc * 16384;
        #pragma unroll
        for (int it = 0; it < 4; it++)
            cp16s(dB0 + so + it * 4096, sb + it * 1024);
        cp_commit();
    };

    // ---- warp fragment constants ----
    const int wid = tid >> 5, lane = tid & 31;
    const int wm = wid >> 2, wn = wid & 3;        // warp tile 64x32
    const int g = lane >> 2, tig = lane & 3;
    const int koffA0 = (4 * tig) ^ ((g & 1) << 4);
    const int koffA1 = koffA0 ^ 16;
    const int koffB0 = (4 * tig) ^ bswz_of(g);
    const int koffB1 = koffB0 ^ 16;
    const int aoff = (wm * 64 + g) * 32;
    const int boff = (wn * 32 + g) * 32;

    float c[4][4][4];
    #pragma unroll
    for (int i = 0; i < 4; i++)
        #pragma unroll
        for (int j = 0; j < 4; j++)
            #pragma unroll
            for (int q = 0; q < 4; q++) c[i][j][q] = 0.f;

    prefetch(0);
    prefetch(1);

    #pragma unroll 1
    for (int kc = 0; kc < NC; kc++) {
        if (kc + 1 < NC) cp_wait<1>(); else cp_wait<0>();
        __syncthreads();                 // kc data visible to all; stage (kc+2)%3 free (== (kc-1)%3)
        if (kc + 2 < NC) prefetch(kc + 2);

        const int st = kc % 3;
        const float* Ab = As + st * 4096 + aoff;
        const float* Bb = Bs + st * 4096 + boff;

        #pragma unroll
        for (int h = 0; h < 2; h++) {
            const int kA = h ? koffA1 : koffA0;
            const int kB = h ? koffB1 : koffB0;
            float4 bb[4], alo[4], ahi[4];
            #pragma unroll
            for (int nf = 0; nf < 4; nf++)
                bb[nf] = *(const float4*)(Bb + nf * 256 + kB);
            #pragma unroll
            for (int mf = 0; mf < 4; mf++) {
                alo[mf] = *(const float4*)(Ab + mf * 512 + kA);
                ahi[mf] = *(const float4*)(Ab + mf * 512 + 256 + kA);
            }
            #pragma unroll
            for (int s = 0; s < 2; s++)
                #pragma unroll
                for (int mf = 0; mf < 4; mf++) {
                    unsigned a0 = __float_as_uint(s ? alo[mf].z : alo[mf].x);
                    unsigned a2 = __float_as_uint(s ? alo[mf].w : alo[mf].y);
                    unsigned a1 = __float_as_uint(s ? ahi[mf].z : ahi[mf].x);
                    unsigned a3 = __float_as_uint(s ? ahi[mf].w : ahi[mf].y);
                    #pragma unroll
                    for (int nf = 0; nf < 4; nf++)
                        mma8(c[mf][nf], a0, a1, a2, a3,
                             s ? bb[nf].z : bb[nf].x, s ? bb[nf].w : bb[nf].y);
                }
        }
    }

    // epilogue: y = s*acc + t, ELU, tf32-round
    size_t rowbase = (size_t)tile * 128;
    #pragma unroll
    for (int nf = 0; nf < 4; nf++) {
        int col = n0 + wn * 32 + nf * 8 + 2 * tig;
        float s0 = __ldg(sc + col), s1 = __ldg(sc + col + 1);
        float t0 = __ldg(sh + col), t1 = __ldg(sh + col + 1);
        #pragma unroll
        for (int mf = 0; mf < 4; mf++) {
            int r = wm * 64 + mf * 16 + g;
            float2 v01, v23;
            v01.x = actf(s0 * c[mf][nf][0] + t0);
            v01.y = actf(s1 * c[mf][nf][1] + t1);
            v23.x = actf(s0 * c[mf][nf][2] + t0);
            v23.y = actf(s1 * c[mf][nf][3] + t1);
            *(float2*)(outp + (rowbase + r) * 512 + col)     = v01;
            *(float2*)(outp + (rowbase + r + 8) * 512 + col) = v23;
        }
    }
}

// ---------------- head kernel: [128][512] @ [512][32] + softmax/ELU + dist ----------------
__global__ void __launch_bounds__(256, 1)
head_kernel(const float* __restrict__ A,
            const float* __restrict__ Wt,    // [32 n][512 k] tf32
            const float* __restrict__ dist,
            float* __restrict__ out)
{
    extern __shared__ float hsm[];
    float* Bp = hsm;                 // 16384
    float* As = hsm + 16384;         // 8192
    float* sZ = hsm + 16384 + 8192;  // 128*33

    const int tid  = threadIdx.x;
    const int tile = blockIdx.x;

    #pragma unroll
    for (int it = 0; it < 16; it++) {
        int o = tid + it * 256;
        int n = o >> 7, ks = o & 127;
        cp16(Bp + n * 512 + ((ks * 4) ^ bswz_of(n)), Wt + (size_t)n * 512 + ks * 4);
    }

    auto loadA = [&](int kc, int buf) {
        #pragma unroll
        for (int it = 0; it < 4; it++) {
            int o = tid + it * 256;
            int r = o >> 3, sg = o & 7;
            cp16(As + buf * 4096 + r * 32 + ((sg * 4) ^ ((r & 1) << 4)),
                 A + (size_t)(tile * 128 + r) * 512 + kc * 32 + sg * 4);
        }
    };

    const int wid = tid >> 5, lane = tid & 31;
    const int g = lane >> 2, tig = lane & 3;
    const int aswz = (g & 1) << 4;
    const int bswz = bswz_of(g);
    int koffA[2], koffB[2];
    koffA[0] = (4 * tig) ^ aswz;  koffA[1] = (16 + 4 * tig) ^ aswz;
    koffB[0] = (4 * tig) ^ bswz;  koffB[1] = (16 + 4 * tig) ^ bswz;
    const float* pA = As + (wid * 16 + g) * 32;
    const float* pB = Bp + g * 512;

    float c[4][4];
    #pragma unroll
    for (int i = 0; i < 4; i++)
        #pragma unroll
        for (int q = 0; q < 4; q++) c[i][q] = 0.f;

    loadA(0, 0); cp_commit();

    #pragma unroll 1
    for (int kc = 0; kc < 16; kc++) {
        int buf = kc & 1;
        __syncthreads();
        if (kc + 1 < 16) { loadA(kc + 1, buf ^ 1); cp_commit(); cp_wait<1>(); }
        else             { cp_wait<0>(); }
        __syncthreads();

        const float* Ab = pA + buf * 4096;
        const float* Bb = pB + kc * 32;
        #pragma unroll
        for (int h = 0; h < 2; h++) {
            float4 bb[4];
            #pragma unroll
            for (int nf = 0; nf < 4; nf++)
                bb[nf] = *(const float4*)(Bb + nf * 4096 + koffB[h]);
            float4 lo = *(const float4*)(Ab + koffA[h]);
            float4 hi = *(const float4*)(Ab + 256 + koffA[h]);
            #pragma unroll
            for (int s = 0; s < 2; s++) {
                unsigned a0 = __float_as_uint(s ? lo.z : lo.x);
                unsigned a2 = __float_as_uint(s ? lo.w : lo.y);
                unsigned a1 = __float_as_uint(s ? hi.z : hi.x);
                unsigned a3 = __float_as_uint(s ? hi.w : hi.y);
                #pragma unroll
                for (int nf = 0; nf < 4; nf++)
                    mma8(c[nf], a0, a1, a2, a3,
                         s ? bb[nf].z : bb[nf].x, s ? bb[nf].w : bb[nf].y);
            }
        }
    }

    {
        int r0 = wid * 16 + g;
        #pragma unroll
        for (int nf = 0; nf < 4; nf++) {
            int co = nf * 8 + 2 * tig;
            sZ[r0 * 33 + co]           = c[nf][0];
            sZ[r0 * 33 + co + 1]       = c[nf][1];
            sZ[(r0 + 8) * 33 + co]     = c[nf][2];
            sZ[(r0 + 8) * 33 + co + 1] = c[nf][3];
        }
    }
    __syncthreads();

    if (tid < 128) {
        int e = tile * 128 + tid;
        if (e < NEDGES) {
            float z[30];
            #pragma unroll
            for (int k = 0; k < 30; k++) z[k] = sZ[tid * 33 + k] + g_hb[k];
            float m = z[0];
            #pragma unroll
            for (int k = 1; k < 10; k++) m = fmaxf(m, z[k]);
            float ez[10], sum = 0.f;
            #pragma unroll
            for (int k = 0; k < 10; k++) { ez[k] = expf(z[k] - m); sum += ez[k]; }
            float inv = 1.f / sum;
            #pragma unroll
            for (int k = 0; k < 10; k++) out[(size_t)e * 10 + k] = ez[k] * inv;
            #pragma unroll
            for (int k = 0; k < 10; k++) {
                float v = z[10 + k];
                v = v > 0.f ? v : expm1f(v);
                out[5000000u + (size_t)e * 10 + k] = v + 1.1f;
            }
            #pragma unroll
            for (int k = 0; k < 10; k++) {
                float v = z[20 + k];
                v = v > 0.f ? v : expm1f(v);
                out[10000000u + (size_t)e * 10 + k] = v + 1.0f;
            }
            out[15000000u + e] = __ldg(dist + e);
        }
    }
}

// ---------------- launch ----------------
extern "C" void kernel_launch(void* const* d_in, const int* in_sizes, int n_in,
                              void* d_out, int out_size) {
    (void)in_sizes; (void)n_in; (void)out_size;
    const float* h    = (const float*)d_in[0];
    const int*   edges= (const int*)  d_in[1];
    const float* dist = (const float*)d_in[2];
    const float* W0   = (const float*)d_in[3];
    const float* b0   = (const float*)d_in[4];
    const float* Wh   = (const float*)d_in[5];
    const float* bh   = (const float*)d_in[6];
    const float* gm   = (const float*)d_in[7];
    const float* bt   = (const float*)d_in[8];
    const float* mn   = (const float*)d_in[9];
    const float* vr   = (const float*)d_in[10];
    const float* Wpi  = (const float*)d_in[11];
    const float* bpi  = (const float*)d_in[12];
    const float* Wsg  = (const float*)d_in[13];
    const float* bsg  = (const float*)d_in[14];
    const float* Wmu  = (const float*)d_in[15];
    const float* bmu  = (const float*)d_in[16];
    float* out = (float*)d_out;

    const int SMEM_HEAD = (16384 + 8192 + 128 * 33) * 4;   // 115,200 B
    cudaFuncSetAttribute(gemm_kernel<256, true>,  cudaFuncAttributeMaxDynamicSharedMemorySize, SMEM_MAIN_B);
    cudaFuncSetAttribute(gemm_kernel<512, false>, cudaFuncAttributeMaxDynamicSharedMemorySize, SMEM_MAIN_B);
    cudaFuncSetAttribute(head_kernel,             cudaFuncAttributeMaxDynamicSharedMemorySize, SMEM_HEAD);

    float *X1, *X2, *W0t, *Wht, *WHt, *sc, *sh;
    cudaGetSymbolAddress((void**)&X1,  g_X1);
    cudaGetSymbolAddress((void**)&X2,  g_X2);
    cudaGetSymbolAddress((void**)&W0t, g_W0t);
    cudaGetSymbolAddress((void**)&Wht, g_Wht);
    cudaGetSymbolAddress((void**)&WHt, g_WHt);
    cudaGetSymbolAddress((void**)&sc,  g_sc);
    cudaGetSymbolAddress((void**)&sh,  g_sh);

    prep_kernel<<<256, 256>>>(W0, b0, Wh, bh, gm, bt, mn, vr,
                              Wpi, bpi, Wsg, bsg, Wmu, bmu);

    dim3 grid(4, TILES);
    gemm_kernel<256, true ><<<grid, 256, SMEM_MAIN_B>>>(h,  edges,   W0t,                 sc,        sh,        X1);
    gemm_kernel<512, false><<<grid, 256, SMEM_MAIN_B>>>(X1, nullptr, Wht,                 sc + 512,  sh + 512,  X2);
    gemm_kernel<512, false><<<grid, 256, SMEM_MAIN_B>>>(X2, nullptr, Wht + 16 * 512 * 32, sc + 1024, sh + 1024, X1);
    head_kernel<<<TILES, 256, SMEM_HEAD>>>(X1, WHt, dist, out);
}